// round 16
// baseline (speedup 1.0000x reference)
#include <cuda_runtime.h>
#include <math.h>

#define EDGES 65536
#define GRID  4096
#define EPB   (EDGES / GRID)   // 16 edges per block
#define PAIRS (EPB / 2)        // 8 edge-pairs per block
#define OUT_ALL_OFF ((size_t)EDGES * 9 * 128)   // 75497472
#define NSPLIT 29
#define MAXC 24                // padded max entries per task (constexpr-checked)

// ===================== compile-time Wigner-3j + task-table generator =====================
namespace gen {

constexpr int KLA[23]  = {0,1,2,3, 0,1,1,2,2,3, 0,1,1,2,2,3,3, 0,1,2,2,3,3};
constexpr int KLB[23]  = {0,1,2,3, 1,0,2,1,3,2, 2,1,3,0,2,1,3, 3,2,1,3,0,2};
constexpr int KLO[23]  = {0,0,0,0, 1,1,1,1,1,1, 2,2,2,2,2,2,2, 3,3,3,3,3,3};
constexpr int KOFF[23] = {0,1,10,35, 84,93,102,147,192,297,
                          402,427,472,577,602,727,832,
                          1077,1126,1231,1336,1581,1630};
constexpr double FACT[11] = {1.,1.,2.,6.,24.,120.,720.,5040.,40320.,362880.,3628800.};

constexpr double csqrt(double x) {
    if (x <= 0.0) return 0.0;
    double g = (x < 1.0) ? 1.0 : x;
    for (int i = 0; i < 200; i++) g = 0.5 * (g + x / g);
    return g;
}
constexpr int imax2(int a, int b) { return a > b ? a : b; }
constexpr int imin2(int a, int b) { return a < b ? a : b; }

constexpr double su2cg(int j1, int m1, int j2, int m2, int j3, int m3) {
    if (m3 != m1 + m2) return 0.0;
    double pref = csqrt((2.0 * j3 + 1.0) * FACT[j3 + j1 - j2] * FACT[j3 - j1 + j2] *
                        FACT[j1 + j2 - j3] / FACT[j1 + j2 + j3 + 1]);
    pref = pref * csqrt(FACT[j3 + m3] * FACT[j3 - m3] * FACT[j1 - m1] * FACT[j1 + m1] *
                        FACT[j2 - m2] * FACT[j2 + m2]);
    int kmin = imax2(0, imax2(j2 - j3 - m1, j1 - j3 + m2));
    int kmax = imin2(j1 + j2 - j3, imin2(j1 - m1, j2 + m2));
    double s = 0.0;
    for (int k = kmin; k <= kmax; k++) {
        double term = 1.0 / (FACT[k] * FACT[j1 + j2 - j3 - k] * FACT[j1 - m1 - k] *
                             FACT[j2 + m2 - k] * FACT[j3 - j2 + m1 + k] * FACT[j3 - j1 - m2 + k]);
        s += (k & 1) ? -term : term;
    }
    return pref * s;
}

struct CD { double re; double im; };
constexpr CD cmulc(CD a, CD b) {
    return CD{a.re * b.re - a.im * b.im, a.re * b.im + a.im * b.re};
}
constexpr CD negip(int l) {
    int m = l & 3;
    return m == 0 ? CD{1, 0} : m == 1 ? CD{0, -1} : m == 2 ? CD{-1, 0} : CD{0, 1};
}
constexpr double RS = 0.70710678118654752440;

struct QE { int n; int idx[2]; CD v[2]; };

constexpr QE qcol(int l, int c) {
    QE q{};
    CD pref = negip(l);
    int mu = c - l;
    if (mu == 0) { q.n = 1; q.idx[0] = l; q.v[0] = pref; return q; }
    if (mu > 0) {
        q.n = 2;
        q.idx[0] = l - mu; q.v[0] = CD{pref.re * RS, pref.im * RS};
        double sg = (mu & 1) ? -1.0 : 1.0;
        q.idx[1] = l + mu; q.v[1] = CD{pref.re * sg * RS, pref.im * sg * RS};
        return q;
    }
    int a = -mu;
    q.n = 2;
    q.idx[0] = l - a; q.v[0] = cmulc(pref, CD{0.0, -RS});
    double sg = (a & 1) ? -1.0 : 1.0;
    q.idx[1] = l + a; q.v[1] = cmulc(pref, CD{0.0, sg * RS});
    return q;
}

constexpr QE qrow(int l, int r) {
    QE q{};
    CD pref = negip(l);
    int mu = r - l;
    if (mu == 0) { q.n = 1; q.idx[0] = l; q.v[0] = pref; return q; }
    if (mu < 0) {
        int a = -mu;
        q.n = 2;
        q.idx[0] = l + a; q.v[0] = CD{pref.re * RS, pref.im * RS};
        q.idx[1] = l - a; q.v[1] = cmulc(pref, CD{0.0, -RS});
        return q;
    }
    double sg = (mu & 1) ? -1.0 : 1.0;
    q.n = 2;
    q.idx[0] = l + mu; q.v[0] = CD{pref.re * sg * RS, pref.im * sg * RS};
    q.idx[1] = l - mu; q.v[1] = cmulc(pref, CD{0.0, sg * RS});
    return q;
}

struct SK { int key; int k; };
constexpr SK sdec(int t) {
    if (t < 4)  return SK{t, 0};
    if (t < 22) { int q = t - 4;  return SK{4 + q / 3, q % 3}; }
    if (t < 57) { int q = t - 22; return SK{10 + q / 5, q % 5}; }
    { int q = t - 57; return SK{17 + q / 7, q % 7}; }
}
constexpr int zmapc(int s) { return s + (s >= 22 ? 2 : 0) + (s >= 57 ? 1 : 0); }

struct Tables {
    int wmax[4];             // per warp-group (tasks 32g..32g+31) uniform loop bound
    float cT[MAXC][128];     // transposed coeff streams (zero padded)
    int   sT[MAXC][128];     // packed shuffle sources: srcA | (srcB<<8)
    int tdst[128];
    int tprs[128];
};

constexpr Tables make_tables() {
    Tables T{};
    double w3j[1875] = {};
    for (int key = 0; key < 23; key++) {
        int la = KLA[key], lb = KLB[key], lo = KLO[key];
        int na = 2 * la + 1, nb = 2 * lb + 1, no = 2 * lo + 1;
        double C[343] = {};
        double Cr[245] = {};
        for (int i = 0; i < na; i++)
            for (int k = 0; k < nb; k++)
                for (int m = 0; m < no; m++) {
                    int m1 = i - la, m2 = k - lb, m3 = m - lo;
                    C[(i * nb + k) * no + m] =
                        (m3 == m1 + m2) ? su2cg(la, m1, lb, m2, lo, m3) : 0.0;
                }
        double norm2 = 0.0;
        for (int ja = 0; ja < na; ja++)
            for (int jb = 0; jb < nb; jb++)
                for (int jn = 0; jn < no; jn++) {
                    QE q1 = qcol(la, ja), q2 = qcol(lb, jb), q3 = qrow(lo, jn);
                    double accre = 0.0;
                    for (int a = 0; a < q1.n; a++)
                        for (int b = 0; b < q2.n; b++)
                            for (int c = 0; c < q3.n; c++) {
                                CD qq = cmulc(cmulc(q1.v[a], q2.v[b]),
                                              CD{q3.v[c].re, -q3.v[c].im});
                                double cv = C[(q1.idx[a] * nb + q2.idx[b]) * no + q3.idx[c]];
                                accre += qq.re * cv;
                            }
                    Cr[(ja * nb + jb) * no + jn] = accre;
                    norm2 += accre * accre;
                }
        double inv = 1.0 / csqrt(norm2);
        int n = na * nb * no;
        for (int idx = 0; idx < n; idx++) w3j[KOFF[key] + idx] = Cr[idx] * inv;
    }

    // per-slot nonzero lists
    int scnt[99] = {};
    int soff[99] = {};
    double nzc[1900] = {};
    int    nzs[1900] = {};
    {
        int acc = 0;
        for (int s = 0; s < 99; s++) {
            SK sk = sdec(s);
            int la = KLA[sk.key], lb = KLB[sk.key];
            int na = 2 * la + 1, nb = 2 * lb + 1, no = 2 * KLO[sk.key] + 1;
            soff[s] = acc;
            int cnt = 0;
            for (int i = 0; i < na; i++)
                for (int j = 0; j < nb; j++) {
                    double c = w3j[KOFF[sk.key] + (i * nb + j) * no + sk.k];
                    if (c > 1e-10 || c < -1e-10) {
                        int xi = la * la + i;        // x source lane (0-15)
                        int yj = 16 + lb * lb + j;   // y source lane (16-31)
                        nzc[acc + cnt] = c;
                        nzs[acc + cnt] = xi | (yj << 8);
                        cnt++;
                    }
                }
            scnt[s] = cnt;
            acc += cnt;
        }
    }

    // rank slots by nnz desc (stable); split top NSPLIT across even/odd thread pairs
    int toff[128] = {};
    int tcnt[128] = {};
    for (int s = 0; s < 99; s++) {
        int rank = 0;
        for (int j = 0; j < 99; j++)
            if (scnt[j] > scnt[s] || (scnt[j] == scnt[s] && j < s)) rank++;
        int off = soff[s], cnt = scnt[s], dst = zmapc(s);
        if (rank < NSPLIT) {
            int p0 = 2 * rank;
            int c1 = (cnt + 1) >> 1;
            toff[p0] = off;          tcnt[p0] = c1;       T.tdst[p0] = dst;  T.tprs[p0] = 1;
            toff[p0 + 1] = off + c1; tcnt[p0 + 1] = cnt - c1; T.tdst[p0 + 1] = -1; T.tprs[p0 + 1] = 0;
        } else {
            int p = 2 * NSPLIT + (rank - NSPLIT);   // 58..127
            toff[p] = off; tcnt[p] = cnt; T.tdst[p] = dst; T.tprs[p] = 0;
        }
    }

    // transposed, padded streams + per-warp-group uniform bounds
    for (int g = 0; g < 4; g++) {
        int m = 0;
        for (int p = 32 * g; p < 32 * g + 32; p++) m = imax2(m, tcnt[p]);
        T.wmax[g] = m;
    }
    for (int p = 0; p < 128; p++)
        for (int n = 0; n < MAXC; n++) {
            if (n < tcnt[p]) {
                T.cT[n][p] = (float)nzc[toff[p] + n];   // OOB here = compile error (fail-closed)
                T.sT[n][p] = nzs[toff[p] + n];
            } else {
                T.cT[n][p] = 0.0f;
                T.sT[n][p] = 0;                          // shfl lane 0, coeff 0 -> no-op
            }
        }
    return T;
}

} // namespace gen

__device__ constexpr gen::Tables g_tab = gen::make_tables();

// ================= main kernel: 256 threads, role-split, edge pairs =================
__device__ __forceinline__ float fsig(float v) { return 1.0f / (1.0f + __expf(-v)); }

__global__ void __launch_bounds__(256, 6)
cg_main_kernel(const float* __restrict__ x, const float* __restrict__ y,
               const float* __restrict__ wcg, const float* __restrict__ bcg,
               const float* __restrict__ wall, const float* __restrict__ ball,
               float* __restrict__ out) {
    __shared__ __align__(8) float2 sCS[MAXC][128];     // fused (coeff, src-bits) streams
    __shared__ __align__(16) float sZ[2][2][104];      // [pair parity][edge-in-pair]
    __shared__ float sWall[35];
    __shared__ float sBall[4];

    int t = threadIdx.x;
    int w = t >> 5, lane = t & 31;
    // interleave the two constexpr tables into one float2 stream (one-time cost)
    for (int i = t; i < MAXC * 128; i += 256) {
        int n = i >> 7, p = i & 127;
        sCS[n][p] = make_float2(g_tab.cT[n][p], __int_as_float(g_tab.sT[n][p]));
    }
    if (t < 35) sWall[t] = wall[t];
    if (t < 4) sBall[t] = ball[t];

    // phase-1 task: table repeats every 128 threads; upper half handles edge+1
    int tt = t & 127;
    int myE = t >> 7;                      // 0 or 1 within pair
    int wm = g_tab.wmax[(t >> 5) & 3];     // warp-uniform loop bound
    int tdst = g_tab.tdst[tt], tpair = g_tab.tprs[tt];

    // role-split weights in one register array (role is warp-uniform)
    float rw[16];
    int ch;
    if (t < 128) {
        ch = t;
        rw[0] = wcg[ch]; rw[1] = wcg[128 + ch]; rw[2] = wcg[256 + ch]; rw[3] = wcg[384 + ch];
        rw[4] = bcg[ch];
        rw[5] = wcg[512 + ch]; rw[6] = wcg[768 + ch]; rw[7] = wcg[1024 + ch]; rw[8] = wcg[1280 + ch];
        rw[9] = bcg[128 + ch];
        rw[10] = wcg[1536 + ch]; rw[11] = wcg[1664 + ch]; rw[12] = wcg[1792 + ch];
        rw[13] = wcg[1920 + ch]; rw[14] = wcg[2048 + ch]; rw[15] = wcg[2176 + ch];
    } else {
        ch = t - 128;
        rw[0] = wcg[640 + ch]; rw[1] = wcg[896 + ch]; rw[2] = wcg[1152 + ch]; rw[3] = wcg[1408 + ch];
        rw[4] = bcg[256 + ch];
        rw[5] = wcg[2304 + ch]; rw[6] = wcg[2432 + ch]; rw[7] = wcg[2560 + ch];
        rw[8] = wcg[2688 + ch]; rw[9] = wcg[2816 + ch]; rw[10] = wcg[2944 + ch];
        rw[11] = wcg[3072 + ch];
        rw[12] = 0.f; rw[13] = 0.f; rw[14] = 0.f; rw[15] = 0.f;
    }

    int e0 = blockIdx.x * EPB;
    // warp w's edge within the pair: 0 for warps 0-3, 1 for warps 4-7
    int weoff = (w >= 4) ? 1 : 0;
    float pre;
    {
        int e = e0 + weoff;
        pre = (lane < 16) ? x[(size_t)e * 16 + lane] : y[(size_t)e * 16 + (lane - 16)];
    }

    // order cooperative stream/sWall/sBall loads before any phase-1/phase-2 reads
    __syncthreads();

    for (int pi = 0; pi < PAIRS; ++pi) {
        int eb = e0 + 2 * pi;
        float v = pre;                                  // this warp's edge x/y
        if (pi + 1 < PAIRS) {
            int en = eb + 2 + weoff;
            pre = (lane < 16) ? x[(size_t)en * 16 + lane] : y[(size_t)en * 16 + (lane - 16)];
        }

        // ---- phase 1: shuffle-gather sparse z (one LDS.64 per entry, uniform loop) ----
        float* zb = sZ[pi & 1][myE];
        {
            float acc = 0.0f;
            for (int n = 0; n < wm; n++) {
                float2 e2 = sCS[n][tt];
                int s = __float_as_int(e2.y);
                float xa = __shfl_sync(0xffffffffu, v, s & 31);
                float yb = __shfl_sync(0xffffffffu, v, (s >> 8) & 31);
                acc = fmaf(e2.x, xa * yb, acc);
            }
            float oth = __shfl_down_sync(0xffffffffu, acc, 1);
            if (tpair) acc += oth;
            if (tdst >= 0) zb[tdst] = acc;
        }
        __syncthreads();   // one barrier per pair

        // ---- phase 2: role-split outputs for both edges ----
        const float S1 = 0.70710678118654752f;   // sqrt(3/6)
        const float S2 = 0.84515425472851657f;   // sqrt(5/7)
        if (t < 128) {
            // role A: rows 0-3 (scv + gated l=1)
#pragma unroll
            for (int el = 0; el < 2; el++) {
                const float* Z = sZ[pi & 1][el];
                float4 z0 = *(const float4*)Z;
                float v0 = fmaf(z0.x, rw[0], fmaf(z0.y, rw[1], fmaf(z0.z, rw[2], z0.w * rw[3])));
                v0 = 0.5f * v0 + rw[4];
                float scv = v0 * fsig(v0);
                float g0 = fmaf(z0.x, rw[5], fmaf(z0.y, rw[6], fmaf(z0.z, rw[7], z0.w * rw[8])));
                g0 = fsig(0.5f * g0 + rw[9]);

                float u0, u1, u2;
                {
                    float4 v4;
                    v4 = *(const float4*)(Z + 4);
                    u0 = v4.x * rw[10]; u1 = v4.y * rw[10]; u2 = v4.z * rw[10]; u0 = fmaf(v4.w, rw[11], u0);
                    v4 = *(const float4*)(Z + 8);
                    u1 = fmaf(v4.x, rw[11], u1); u2 = fmaf(v4.y, rw[11], u2);
                    u0 = fmaf(v4.z, rw[12], u0); u1 = fmaf(v4.w, rw[12], u1);
                    v4 = *(const float4*)(Z + 12);
                    u2 = fmaf(v4.x, rw[12], u2); u0 = fmaf(v4.y, rw[13], u0);
                    u1 = fmaf(v4.z, rw[13], u1); u2 = fmaf(v4.w, rw[13], u2);
                    v4 = *(const float4*)(Z + 16);
                    u0 = fmaf(v4.x, rw[14], u0); u1 = fmaf(v4.y, rw[14], u1);
                    u2 = fmaf(v4.z, rw[14], u2); u0 = fmaf(v4.w, rw[15], u0);
                    float2 v2 = *(const float2*)(Z + 20);
                    u1 = fmaf(v2.x, rw[15], u1); u2 = fmaf(v2.y, rw[15], u2);
                }
                size_t base = ((size_t)(eb + el) * 9) * 128 + ch;
                out[base] = scv;
                float gg = S1 * g0;
                out[base + 128] = u0 * gg;
                out[base + 256] = u1 * gg;
                out[base + 384] = u2 * gg;
            }
            // ---- "all" branch: threads 0-31 cover both edges ----
            if (t < 32) {
                int el = t >> 4;
                int k = t & 15;
                const float* Z = sZ[pi & 1][el];
                float4 z0 = *(const float4*)Z;
                float* oa = out + OUT_ALL_OFF + (size_t)(eb + el) * 16;
                if (k == 0) {
                    float vv = 0.5f * (z0.x * sWall[0] + z0.y * sWall[1] + z0.z * sWall[2] + z0.w * sWall[3]) + sBall[0];
                    oa[0] = vv * fsig(vv);
                } else if (k < 4) {
                    int kk = k - 1;
                    float g = fsig(0.5f * (z0.x * sWall[4] + z0.y * sWall[7] + z0.z * sWall[10] + z0.w * sWall[13]) + sBall[1]);
                    float u = 0.f;
#pragma unroll
                    for (int p = 0; p < 6; p++) u += Z[4 + 3 * p + kk] * sWall[16 + p];
                    oa[k] = 0.70710678118654752f * u * g;
                } else if (k < 9) {
                    int kk = k - 4;
                    float g = fsig(0.5f * (z0.x * sWall[5] + z0.y * sWall[8] + z0.z * sWall[11] + z0.w * sWall[14]) + sBall[2]);
                    float u = 0.f;
#pragma unroll
                    for (int p = 0; p < 7; p++) u += Z[24 + 5 * p + kk] * sWall[22 + p];
                    oa[k] = 0.84515425472851657f * u * g;
                } else {
                    int kk = k - 9;
                    float g = fsig(0.5f * (z0.x * sWall[6] + z0.y * sWall[9] + z0.z * sWall[12] + z0.w * sWall[15]) + sBall[3]);
                    float u = 0.f;
#pragma unroll
                    for (int p = 0; p < 6; p++) u += Z[60 + 7 * p + kk] * sWall[29 + p];
                    oa[k] = 1.08012344973464367f * u * g;   // sqrt(7/6)
                }
            }
        } else {
            // role B: rows 4-8 (gated l=2)
#pragma unroll
            for (int el = 0; el < 2; el++) {
                const float* Z = sZ[pi & 1][el];
                float4 z0 = *(const float4*)Z;
                float g1 = fmaf(z0.x, rw[0], fmaf(z0.y, rw[1], fmaf(z0.z, rw[2], z0.w * rw[3])));
                g1 = fsig(0.5f * g1 + rw[4]);

                float q0, q1, q2, q3, q4;
                {
                    float4 v4;
                    v4 = *(const float4*)(Z + 24);
                    q0 = v4.x * rw[5]; q1 = v4.y * rw[5]; q2 = v4.z * rw[5]; q3 = v4.w * rw[5];
                    v4 = *(const float4*)(Z + 28);
                    q4 = v4.x * rw[5]; q0 = fmaf(v4.y, rw[6], q0); q1 = fmaf(v4.z, rw[6], q1); q2 = fmaf(v4.w, rw[6], q2);
                    v4 = *(const float4*)(Z + 32);
                    q3 = fmaf(v4.x, rw[6], q3); q4 = fmaf(v4.y, rw[6], q4); q0 = fmaf(v4.z, rw[7], q0); q1 = fmaf(v4.w, rw[7], q1);
                    v4 = *(const float4*)(Z + 36);
                    q2 = fmaf(v4.x, rw[7], q2); q3 = fmaf(v4.y, rw[7], q3); q4 = fmaf(v4.z, rw[7], q4); q0 = fmaf(v4.w, rw[8], q0);
                    v4 = *(const float4*)(Z + 40);
                    q1 = fmaf(v4.x, rw[8], q1); q2 = fmaf(v4.y, rw[8], q2); q3 = fmaf(v4.z, rw[8], q3); q4 = fmaf(v4.w, rw[8], q4);
                    v4 = *(const float4*)(Z + 44);
                    q0 = fmaf(v4.x, rw[9], q0); q1 = fmaf(v4.y, rw[9], q1); q2 = fmaf(v4.z, rw[9], q2); q3 = fmaf(v4.w, rw[9], q3);
                    v4 = *(const float4*)(Z + 48);
                    q4 = fmaf(v4.x, rw[9], q4); q0 = fmaf(v4.y, rw[10], q0); q1 = fmaf(v4.z, rw[10], q1); q2 = fmaf(v4.w, rw[10], q2);
                    v4 = *(const float4*)(Z + 52);
                    q3 = fmaf(v4.x, rw[10], q3); q4 = fmaf(v4.y, rw[10], q4); q0 = fmaf(v4.z, rw[11], q0); q1 = fmaf(v4.w, rw[11], q1);
                    v4 = *(const float4*)(Z + 56);   // Z[59] is padding (lane discarded)
                    q2 = fmaf(v4.x, rw[11], q2); q3 = fmaf(v4.y, rw[11], q3); q4 = fmaf(v4.z, rw[11], q4);
                }
                size_t base = ((size_t)(eb + el) * 9) * 128 + ch;
                float hh = S2 * g1;
                out[base + 512] = q0 * hh;
                out[base + 640] = q1 * hh;
                out[base + 768] = q2 * hh;
                out[base + 896] = q3 * hh;
                out[base + 1024] = q4 * hh;
            }
        }
        // no trailing barrier: ping-pong over pair parity + the per-pair barrier
        // give the needed ordering (reaching pair pi+2's phase-1 writes requires
        // passing pair pi+1's barrier, which is after all pair-pi phase-2 reads).
    }
}

extern "C" void kernel_launch(void* const* d_in, const int* in_sizes, int n_in,
                              void* d_out, int out_size) {
    const float* x    = (const float*)d_in[0];
    const float* y    = (const float*)d_in[1];
    const float* wcg  = (const float*)d_in[2];
    const float* bcg  = (const float*)d_in[3];
    const float* wall = (const float*)d_in[4];
    const float* ball = (const float*)d_in[5];
    float* out = (float*)d_out;

    cg_main_kernel<<<GRID, 256>>>(x, y, wcg, bcg, wall, ball, out);
}

// round 17
// speedup vs baseline: 1.2290x; 1.2290x over previous
#include <cuda_runtime.h>
#include <math.h>

#define EDGES 65536
#define GRID  4096
#define EPB   (EDGES / GRID)   // 16 edges per block
#define QUADS (EPB / 4)        // 4 quads (of 4 edges) per block
#define OUT_ALL_OFF ((size_t)EDGES * 9 * 128)   // 75497472
#define NSPLIT 29
#define MAXC 24                // padded max entries per task (constexpr-checked)

// ===================== compile-time Wigner-3j + task-table generator =====================
namespace gen {

constexpr int KLA[23]  = {0,1,2,3, 0,1,1,2,2,3, 0,1,1,2,2,3,3, 0,1,2,2,3,3};
constexpr int KLB[23]  = {0,1,2,3, 1,0,2,1,3,2, 2,1,3,0,2,1,3, 3,2,1,3,0,2};
constexpr int KLO[23]  = {0,0,0,0, 1,1,1,1,1,1, 2,2,2,2,2,2,2, 3,3,3,3,3,3};
constexpr int KOFF[23] = {0,1,10,35, 84,93,102,147,192,297,
                          402,427,472,577,602,727,832,
                          1077,1126,1231,1336,1581,1630};
constexpr double FACT[11] = {1.,1.,2.,6.,24.,120.,720.,5040.,40320.,362880.,3628800.};

constexpr double csqrt(double x) {
    if (x <= 0.0) return 0.0;
    double g = (x < 1.0) ? 1.0 : x;
    for (int i = 0; i < 200; i++) g = 0.5 * (g + x / g);
    return g;
}
constexpr int imax2(int a, int b) { return a > b ? a : b; }
constexpr int imin2(int a, int b) { return a < b ? a : b; }

constexpr double su2cg(int j1, int m1, int j2, int m2, int j3, int m3) {
    if (m3 != m1 + m2) return 0.0;
    double pref = csqrt((2.0 * j3 + 1.0) * FACT[j3 + j1 - j2] * FACT[j3 - j1 + j2] *
                        FACT[j1 + j2 - j3] / FACT[j1 + j2 + j3 + 1]);
    pref = pref * csqrt(FACT[j3 + m3] * FACT[j3 - m3] * FACT[j1 - m1] * FACT[j1 + m1] *
                        FACT[j2 - m2] * FACT[j2 + m2]);
    int kmin = imax2(0, imax2(j2 - j3 - m1, j1 - j3 + m2));
    int kmax = imin2(j1 + j2 - j3, imin2(j1 - m1, j2 + m2));
    double s = 0.0;
    for (int k = kmin; k <= kmax; k++) {
        double term = 1.0 / (FACT[k] * FACT[j1 + j2 - j3 - k] * FACT[j1 - m1 - k] *
                             FACT[j2 + m2 - k] * FACT[j3 - j2 + m1 + k] * FACT[j3 - j1 - m2 + k]);
        s += (k & 1) ? -term : term;
    }
    return pref * s;
}

struct CD { double re; double im; };
constexpr CD cmulc(CD a, CD b) {
    return CD{a.re * b.re - a.im * b.im, a.re * b.im + a.im * b.re};
}
constexpr CD negip(int l) {
    int m = l & 3;
    return m == 0 ? CD{1, 0} : m == 1 ? CD{0, -1} : m == 2 ? CD{-1, 0} : CD{0, 1};
}
constexpr double RS = 0.70710678118654752440;

struct QE { int n; int idx[2]; CD v[2]; };

constexpr QE qcol(int l, int c) {
    QE q{};
    CD pref = negip(l);
    int mu = c - l;
    if (mu == 0) { q.n = 1; q.idx[0] = l; q.v[0] = pref; return q; }
    if (mu > 0) {
        q.n = 2;
        q.idx[0] = l - mu; q.v[0] = CD{pref.re * RS, pref.im * RS};
        double sg = (mu & 1) ? -1.0 : 1.0;
        q.idx[1] = l + mu; q.v[1] = CD{pref.re * sg * RS, pref.im * sg * RS};
        return q;
    }
    int a = -mu;
    q.n = 2;
    q.idx[0] = l - a; q.v[0] = cmulc(pref, CD{0.0, -RS});
    double sg = (a & 1) ? -1.0 : 1.0;
    q.idx[1] = l + a; q.v[1] = cmulc(pref, CD{0.0, sg * RS});
    return q;
}

constexpr QE qrow(int l, int r) {
    QE q{};
    CD pref = negip(l);
    int mu = r - l;
    if (mu == 0) { q.n = 1; q.idx[0] = l; q.v[0] = pref; return q; }
    if (mu < 0) {
        int a = -mu;
        q.n = 2;
        q.idx[0] = l + a; q.v[0] = CD{pref.re * RS, pref.im * RS};
        q.idx[1] = l - a; q.v[1] = cmulc(pref, CD{0.0, -RS});
        return q;
    }
    double sg = (mu & 1) ? -1.0 : 1.0;
    q.n = 2;
    q.idx[0] = l + mu; q.v[0] = CD{pref.re * sg * RS, pref.im * sg * RS};
    q.idx[1] = l - mu; q.v[1] = cmulc(pref, CD{0.0, sg * RS});
    return q;
}

struct SK { int key; int k; };
constexpr SK sdec(int t) {
    if (t < 4)  return SK{t, 0};
    if (t < 22) { int q = t - 4;  return SK{4 + q / 3, q % 3}; }
    if (t < 57) { int q = t - 22; return SK{10 + q / 5, q % 5}; }
    { int q = t - 57; return SK{17 + q / 7, q % 7}; }
}
constexpr int zmapc(int s) { return s + (s >= 22 ? 2 : 0) + (s >= 57 ? 1 : 0); }

struct Tables {
    int wmax[4];             // per warp-group (tasks 32g..32g+31) uniform loop bound
    float cT[MAXC][128];     // transposed coeff streams (zero padded)
    int   sT[MAXC][128];     // packed shuffle sources: srcA | (srcB<<8)
    int tdst[128];
    int tprs[128];
};

constexpr Tables make_tables() {
    Tables T{};
    double w3j[1875] = {};
    for (int key = 0; key < 23; key++) {
        int la = KLA[key], lb = KLB[key], lo = KLO[key];
        int na = 2 * la + 1, nb = 2 * lb + 1, no = 2 * lo + 1;
        double C[343] = {};
        double Cr[245] = {};
        for (int i = 0; i < na; i++)
            for (int k = 0; k < nb; k++)
                for (int m = 0; m < no; m++) {
                    int m1 = i - la, m2 = k - lb, m3 = m - lo;
                    C[(i * nb + k) * no + m] =
                        (m3 == m1 + m2) ? su2cg(la, m1, lb, m2, lo, m3) : 0.0;
                }
        double norm2 = 0.0;
        for (int ja = 0; ja < na; ja++)
            for (int jb = 0; jb < nb; jb++)
                for (int jn = 0; jn < no; jn++) {
                    QE q1 = qcol(la, ja), q2 = qcol(lb, jb), q3 = qrow(lo, jn);
                    double accre = 0.0;
                    for (int a = 0; a < q1.n; a++)
                        for (int b = 0; b < q2.n; b++)
                            for (int c = 0; c < q3.n; c++) {
                                CD qq = cmulc(cmulc(q1.v[a], q2.v[b]),
                                              CD{q3.v[c].re, -q3.v[c].im});
                                double cv = C[(q1.idx[a] * nb + q2.idx[b]) * no + q3.idx[c]];
                                accre += qq.re * cv;
                            }
                    Cr[(ja * nb + jb) * no + jn] = accre;
                    norm2 += accre * accre;
                }
        double inv = 1.0 / csqrt(norm2);
        int n = na * nb * no;
        for (int idx = 0; idx < n; idx++) w3j[KOFF[key] + idx] = Cr[idx] * inv;
    }

    // per-slot nonzero lists
    int scnt[99] = {};
    int soff[99] = {};
    double nzc[1900] = {};
    int    nzs[1900] = {};
    {
        int acc = 0;
        for (int s = 0; s < 99; s++) {
            SK sk = sdec(s);
            int la = KLA[sk.key], lb = KLB[sk.key];
            int na = 2 * la + 1, nb = 2 * lb + 1, no = 2 * KLO[sk.key] + 1;
            soff[s] = acc;
            int cnt = 0;
            for (int i = 0; i < na; i++)
                for (int j = 0; j < nb; j++) {
                    double c = w3j[KOFF[sk.key] + (i * nb + j) * no + sk.k];
                    if (c > 1e-10 || c < -1e-10) {
                        int xi = la * la + i;        // x source lane (0-15)
                        int yj = 16 + lb * lb + j;   // y source lane (16-31)
                        nzc[acc + cnt] = c;
                        nzs[acc + cnt] = xi | (yj << 8);
                        cnt++;
                    }
                }
            scnt[s] = cnt;
            acc += cnt;
        }
    }

    // rank slots by nnz desc (stable); split top NSPLIT across even/odd thread pairs
    int toff[128] = {};
    int tcnt[128] = {};
    for (int s = 0; s < 99; s++) {
        int rank = 0;
        for (int j = 0; j < 99; j++)
            if (scnt[j] > scnt[s] || (scnt[j] == scnt[s] && j < s)) rank++;
        int off = soff[s], cnt = scnt[s], dst = zmapc(s);
        if (rank < NSPLIT) {
            int p0 = 2 * rank;
            int c1 = (cnt + 1) >> 1;
            toff[p0] = off;          tcnt[p0] = c1;       T.tdst[p0] = dst;  T.tprs[p0] = 1;
            toff[p0 + 1] = off + c1; tcnt[p0 + 1] = cnt - c1; T.tdst[p0 + 1] = -1; T.tprs[p0 + 1] = 0;
        } else {
            int p = 2 * NSPLIT + (rank - NSPLIT);   // 58..127
            toff[p] = off; tcnt[p] = cnt; T.tdst[p] = dst; T.tprs[p] = 0;
        }
    }

    // transposed, padded streams + per-warp-group uniform bounds
    for (int g = 0; g < 4; g++) {
        int m = 0;
        for (int p = 32 * g; p < 32 * g + 32; p++) m = imax2(m, tcnt[p]);
        T.wmax[g] = m;
    }
    for (int p = 0; p < 128; p++)
        for (int n = 0; n < MAXC; n++) {
            if (n < tcnt[p]) {
                T.cT[n][p] = (float)nzc[toff[p] + n];   // OOB here = compile error (fail-closed)
                T.sT[n][p] = nzs[toff[p] + n];
            } else {
                T.cT[n][p] = 0.0f;
                T.sT[n][p] = 0;                          // shfl lane 0, coeff 0 -> no-op
            }
        }
    return T;
}

} // namespace gen

__device__ constexpr gen::Tables g_tab = gen::make_tables();

// ================= main kernel: 256 threads, role-split, quad edges =================
__device__ __forceinline__ float fsig(float v) { return 1.0f / (1.0f + __expf(-v)); }

__global__ void __launch_bounds__(256, 5)
cg_main_kernel(const float* __restrict__ x, const float* __restrict__ y,
               const float* __restrict__ wcg, const float* __restrict__ bcg,
               const float* __restrict__ wall, const float* __restrict__ ball,
               float* __restrict__ out) {
    __shared__ __align__(8) float2 sCS[MAXC][128];     // fused (coeff, src-bits) streams
    __shared__ __align__(16) float sZ[2][4][104];      // [quad parity][edge-in-quad]
    __shared__ float sWall[35];
    __shared__ float sBall[4];

    int t = threadIdx.x;
    int w = t >> 5, lane = t & 31;
    // interleave the two constexpr tables into one float2 stream (one-time cost)
    for (int i = t; i < MAXC * 128; i += 256) {
        int n = i >> 7, p = i & 127;
        sCS[n][p] = make_float2(g_tab.cT[n][p], __int_as_float(g_tab.sT[n][p]));
    }
    if (t < 35) sWall[t] = wall[t];
    if (t < 4) sBall[t] = ball[t];

    // phase-1 task: table repeats every 128 threads; upper half handles odd edges
    int tt = t & 127;
    int myE = t >> 7;                      // 0 or 1 (edge parity within pairs)
    int wm = g_tab.wmax[(t >> 5) & 3];     // warp-uniform loop bound
    int tdst = g_tab.tdst[tt], tpair = g_tab.tprs[tt];

    // role-split weights in one register array (role is warp-uniform)
    float rw[16];
    int ch;
    if (t < 128) {
        ch = t;
        rw[0] = wcg[ch]; rw[1] = wcg[128 + ch]; rw[2] = wcg[256 + ch]; rw[3] = wcg[384 + ch];
        rw[4] = bcg[ch];
        rw[5] = wcg[512 + ch]; rw[6] = wcg[768 + ch]; rw[7] = wcg[1024 + ch]; rw[8] = wcg[1280 + ch];
        rw[9] = bcg[128 + ch];
        rw[10] = wcg[1536 + ch]; rw[11] = wcg[1664 + ch]; rw[12] = wcg[1792 + ch];
        rw[13] = wcg[1920 + ch]; rw[14] = wcg[2048 + ch]; rw[15] = wcg[2176 + ch];
    } else {
        ch = t - 128;
        rw[0] = wcg[640 + ch]; rw[1] = wcg[896 + ch]; rw[2] = wcg[1152 + ch]; rw[3] = wcg[1408 + ch];
        rw[4] = bcg[256 + ch];
        rw[5] = wcg[2304 + ch]; rw[6] = wcg[2432 + ch]; rw[7] = wcg[2560 + ch];
        rw[8] = wcg[2688 + ch]; rw[9] = wcg[2816 + ch]; rw[10] = wcg[2944 + ch];
        rw[11] = wcg[3072 + ch];
        rw[12] = 0.f; rw[13] = 0.f; rw[14] = 0.f; rw[15] = 0.f;
    }

    int e0 = blockIdx.x * EPB;
    // warp w handles edges (quad_base + weoff) and (quad_base + 2 + weoff)
    int weoff = (w >= 4) ? 1 : 0;
    float pre_a, pre_b;
    {
        int ea = e0 + weoff, ebg = e0 + 2 + weoff;
        pre_a = (lane < 16) ? x[(size_t)ea * 16 + lane] : y[(size_t)ea * 16 + (lane - 16)];
        pre_b = (lane < 16) ? x[(size_t)ebg * 16 + lane] : y[(size_t)ebg * 16 + (lane - 16)];
    }

    // order cooperative stream/sWall/sBall loads before any phase-1/phase-2 reads
    __syncthreads();

    for (int qi = 0; qi < QUADS; ++qi) {
        int qb = e0 + 4 * qi;
        float va = pre_a, vb = pre_b;                   // this warp's two edges
        if (qi + 1 < QUADS) {
            int ea = qb + 4 + weoff, ebg = qb + 6 + weoff;
            pre_a = (lane < 16) ? x[(size_t)ea * 16 + lane] : y[(size_t)ea * 16 + (lane - 16)];
            pre_b = (lane < 16) ? x[(size_t)ebg * 16 + lane] : y[(size_t)ebg * 16 + (lane - 16)];
        }

        // ---- phase 1: z for 4 edges; each stream entry serves two edges ----
        {
            float acc0 = 0.0f, acc1 = 0.0f;
            for (int n = 0; n < wm; n++) {
                float2 e2 = sCS[n][tt];
                int s = __float_as_int(e2.y);
                int sa = s & 31, sb = (s >> 8) & 31;
                float xa0 = __shfl_sync(0xffffffffu, va, sa);
                float yb0 = __shfl_sync(0xffffffffu, va, sb);
                float xa1 = __shfl_sync(0xffffffffu, vb, sa);
                float yb1 = __shfl_sync(0xffffffffu, vb, sb);
                acc0 = fmaf(e2.x, xa0 * yb0, acc0);
                acc1 = fmaf(e2.x, xa1 * yb1, acc1);
            }
            float o0 = __shfl_down_sync(0xffffffffu, acc0, 1);
            float o1 = __shfl_down_sync(0xffffffffu, acc1, 1);
            if (tpair) { acc0 += o0; acc1 += o1; }
            if (tdst >= 0) {
                sZ[qi & 1][myE][tdst] = acc0;
                sZ[qi & 1][myE + 2][tdst] = acc1;
            }
        }
        __syncthreads();   // one barrier per quad

        // ---- phase 2: role-split outputs for all 4 edges ----
        const float S1 = 0.70710678118654752f;   // sqrt(3/6)
        const float S2 = 0.84515425472851657f;   // sqrt(5/7)
        if (t < 128) {
            // role A: rows 0-3 (scv + gated l=1)
#pragma unroll
            for (int el = 0; el < 4; el++) {
                const float* Z = sZ[qi & 1][el];
                float4 z0 = *(const float4*)Z;
                float v0 = fmaf(z0.x, rw[0], fmaf(z0.y, rw[1], fmaf(z0.z, rw[2], z0.w * rw[3])));
                v0 = 0.5f * v0 + rw[4];
                float scv = v0 * fsig(v0);
                float g0 = fmaf(z0.x, rw[5], fmaf(z0.y, rw[6], fmaf(z0.z, rw[7], z0.w * rw[8])));
                g0 = fsig(0.5f * g0 + rw[9]);

                float u0, u1, u2;
                {
                    float4 v4;
                    v4 = *(const float4*)(Z + 4);
                    u0 = v4.x * rw[10]; u1 = v4.y * rw[10]; u2 = v4.z * rw[10]; u0 = fmaf(v4.w, rw[11], u0);
                    v4 = *(const float4*)(Z + 8);
                    u1 = fmaf(v4.x, rw[11], u1); u2 = fmaf(v4.y, rw[11], u2);
                    u0 = fmaf(v4.z, rw[12], u0); u1 = fmaf(v4.w, rw[12], u1);
                    v4 = *(const float4*)(Z + 12);
                    u2 = fmaf(v4.x, rw[12], u2); u0 = fmaf(v4.y, rw[13], u0);
                    u1 = fmaf(v4.z, rw[13], u1); u2 = fmaf(v4.w, rw[13], u2);
                    v4 = *(const float4*)(Z + 16);
                    u0 = fmaf(v4.x, rw[14], u0); u1 = fmaf(v4.y, rw[14], u1);
                    u2 = fmaf(v4.z, rw[14], u2); u0 = fmaf(v4.w, rw[15], u0);
                    float2 v2 = *(const float2*)(Z + 20);
                    u1 = fmaf(v2.x, rw[15], u1); u2 = fmaf(v2.y, rw[15], u2);
                }
                size_t base = ((size_t)(qb + el) * 9) * 128 + ch;
                out[base] = scv;
                float gg = S1 * g0;
                out[base + 128] = u0 * gg;
                out[base + 256] = u1 * gg;
                out[base + 384] = u2 * gg;
            }
            // ---- "all" branch: threads 0-63 cover the 4 edges ----
            if (t < 64) {
                int el = t >> 4;
                int k = t & 15;
                const float* Z = sZ[qi & 1][el];
                float4 z0 = *(const float4*)Z;
                float* oa = out + OUT_ALL_OFF + (size_t)(qb + el) * 16;
                if (k == 0) {
                    float vv = 0.5f * (z0.x * sWall[0] + z0.y * sWall[1] + z0.z * sWall[2] + z0.w * sWall[3]) + sBall[0];
                    oa[0] = vv * fsig(vv);
                } else if (k < 4) {
                    int kk = k - 1;
                    float g = fsig(0.5f * (z0.x * sWall[4] + z0.y * sWall[7] + z0.z * sWall[10] + z0.w * sWall[13]) + sBall[1]);
                    float u = 0.f;
#pragma unroll
                    for (int p = 0; p < 6; p++) u += Z[4 + 3 * p + kk] * sWall[16 + p];
                    oa[k] = 0.70710678118654752f * u * g;
                } else if (k < 9) {
                    int kk = k - 4;
                    float g = fsig(0.5f * (z0.x * sWall[5] + z0.y * sWall[8] + z0.z * sWall[11] + z0.w * sWall[14]) + sBall[2]);
                    float u = 0.f;
#pragma unroll
                    for (int p = 0; p < 7; p++) u += Z[24 + 5 * p + kk] * sWall[22 + p];
                    oa[k] = 0.84515425472851657f * u * g;
                } else {
                    int kk = k - 9;
                    float g = fsig(0.5f * (z0.x * sWall[6] + z0.y * sWall[9] + z0.z * sWall[12] + z0.w * sWall[15]) + sBall[3]);
                    float u = 0.f;
#pragma unroll
                    for (int p = 0; p < 6; p++) u += Z[60 + 7 * p + kk] * sWall[29 + p];
                    oa[k] = 1.08012344973464367f * u * g;   // sqrt(7/6)
                }
            }
        } else {
            // role B: rows 4-8 (gated l=2)
#pragma unroll
            for (int el = 0; el < 4; el++) {
                const float* Z = sZ[qi & 1][el];
                float4 z0 = *(const float4*)Z;
                float g1 = fmaf(z0.x, rw[0], fmaf(z0.y, rw[1], fmaf(z0.z, rw[2], z0.w * rw[3])));
                g1 = fsig(0.5f * g1 + rw[4]);

                float q0, q1, q2, q3, q4;
                {
                    float4 v4;
                    v4 = *(const float4*)(Z + 24);
                    q0 = v4.x * rw[5]; q1 = v4.y * rw[5]; q2 = v4.z * rw[5]; q3 = v4.w * rw[5];
                    v4 = *(const float4*)(Z + 28);
                    q4 = v4.x * rw[5]; q0 = fmaf(v4.y, rw[6], q0); q1 = fmaf(v4.z, rw[6], q1); q2 = fmaf(v4.w, rw[6], q2);
                    v4 = *(const float4*)(Z + 32);
                    q3 = fmaf(v4.x, rw[6], q3); q4 = fmaf(v4.y, rw[6], q4); q0 = fmaf(v4.z, rw[7], q0); q1 = fmaf(v4.w, rw[7], q1);
                    v4 = *(const float4*)(Z + 36);
                    q2 = fmaf(v4.x, rw[7], q2); q3 = fmaf(v4.y, rw[7], q3); q4 = fmaf(v4.z, rw[7], q4); q0 = fmaf(v4.w, rw[8], q0);
                    v4 = *(const float4*)(Z + 40);
                    q1 = fmaf(v4.x, rw[8], q1); q2 = fmaf(v4.y, rw[8], q2); q3 = fmaf(v4.z, rw[8], q3); q4 = fmaf(v4.w, rw[8], q4);
                    v4 = *(const float4*)(Z + 44);
                    q0 = fmaf(v4.x, rw[9], q0); q1 = fmaf(v4.y, rw[9], q1); q2 = fmaf(v4.z, rw[9], q2); q3 = fmaf(v4.w, rw[9], q3);
                    v4 = *(const float4*)(Z + 48);
                    q4 = fmaf(v4.x, rw[9], q4); q0 = fmaf(v4.y, rw[10], q0); q1 = fmaf(v4.z, rw[10], q1); q2 = fmaf(v4.w, rw[10], q2);
                    v4 = *(const float4*)(Z + 52);
                    q3 = fmaf(v4.x, rw[10], q3); q4 = fmaf(v4.y, rw[10], q4); q0 = fmaf(v4.z, rw[11], q0); q1 = fmaf(v4.w, rw[11], q1);
                    v4 = *(const float4*)(Z + 56);   // Z[59] is padding (lane discarded)
                    q2 = fmaf(v4.x, rw[11], q2); q3 = fmaf(v4.y, rw[11], q3); q4 = fmaf(v4.z, rw[11], q4);
                }
                size_t base = ((size_t)(qb + el) * 9) * 128 + ch;
                float hh = S2 * g1;
                out[base + 512] = q0 * hh;
                out[base + 640] = q1 * hh;
                out[base + 768] = q2 * hh;
                out[base + 896] = q3 * hh;
                out[base + 1024] = q4 * hh;
            }
        }
        // no trailing barrier: ping-pong over quad parity + the per-quad barrier
        // give the needed ordering (reaching quad qi+2's phase-1 writes requires
        // passing quad qi+1's barrier, which is after all quad-qi phase-2 reads).
    }
}

extern "C" void kernel_launch(void* const* d_in, const int* in_sizes, int n_in,
                              void* d_out, int out_size) {
    const float* x    = (const float*)d_in[0];
    const float* y    = (const float*)d_in[1];
    const float* wcg  = (const float*)d_in[2];
    const float* bcg  = (const float*)d_in[3];
    const float* wall = (const float*)d_in[4];
    const float* ball = (const float*)d_in[5];
    float* out = (float*)d_out;

    cg_main_kernel<<<GRID, 256>>>(x, y, wcg, bcg, wall, ball, out);
}